// round 5
// baseline (speedup 1.0000x reference)
#include <cuda_runtime.h>
#include <stdint.h>

#define NN   2048          // num_nodes
#define W    64            // words per bitmask row = NN/32
#define FDIM 8             // edge feature dim
#define NB   512           // fused-kernel blocks (NN/4)

__device__ uint32_t g_adj [NN * W];   // zero at load; re-zeroed by k_attr
__device__ uint32_t g_comb[NN * W];
__device__ int      g_off  [NN];
__device__ unsigned long long g_status[NB];   // lookback: (flag<<32)|count

// ---------------------------------------------------------------------------
// init: fill index region with -1.0f, attr region with 0.0f  (side stream)
// ---------------------------------------------------------------------------
__global__ void k_init(float* __restrict__ out, int emax)
{
    const int64_t idx_words = (int64_t)emax * 2;
    const int64_t total     = (int64_t)emax * (2 + FDIM);
    const int64_t n4        = total >> 2;
    const float4 neg = make_float4(-1.f, -1.f, -1.f, -1.f);
    const float4 zer = make_float4( 0.f,  0.f,  0.f,  0.f);

    int64_t stride = (int64_t)gridDim.x * blockDim.x;
    for (int64_t i = (int64_t)blockIdx.x * blockDim.x + threadIdx.x;
         i < n4; i += stride)
        ((float4*)out)[i] = ((i << 2) < idx_words) ? neg : zer;
}

// ---------------------------------------------------------------------------
// scatter: set adjacency bits; also reset lookback statuses for this call
// ---------------------------------------------------------------------------
__global__ void k_scatter(const int* __restrict__ src,
                          const int* __restrict__ dst, int E)
{
    int e = blockIdx.x * blockDim.x + threadIdx.x;
    if (e < NB) g_status[e] = 0ull;
    if (e >= E) return;
    int s = src[e], d = dst[e];
    atomicOr(&g_adj[s * W + (d >> 5)], 1u << (d & 31));
}

// ---------------------------------------------------------------------------
// fused: expand (two-hop OR) + decoupled-lookback scan + emit, one kernel.
// grid = NB blocks x 256 threads; 4 rows per block; thread = (row g, word w).
// ---------------------------------------------------------------------------
__global__ __launch_bounds__(256) void k_fused(float* __restrict__ out, int emax)
{
    __shared__ uint16_t nbr[4][NN];
    __shared__ int wtot[4][2];     // phase-A 64-thread scan carry
    __shared__ int etot[4][2];     // phase-C 64-thread scan carry
    __shared__ int rcnt[4];        // per-row comb popcount
    __shared__ int sbexcl;         // block-exclusive global offset

    const int tid  = threadIdx.x;
    const int bid  = blockIdx.x;
    const int g    = tid >> 6;     // row in block 0..3
    const int w    = tid & 63;     // word 0..63
    const int r    = (bid << 2) + g;
    const int lane = w & 31, hw = w >> 5;

    // ---- Phase A: expand ---------------------------------------------------
    uint32_t a = g_adj[r * W + w];

    int pc = __popc(a);
    int x = pc;
    #pragma unroll
    for (int o = 1; o < 32; o <<= 1) {
        int v = __shfl_up_sync(0xffffffffu, x, o);
        if (lane >= o) x += v;
    }
    if (lane == 31) wtot[g][hw] = x;
    __syncthreads();
    int excl = x - pc + (hw ? wtot[g][0] : 0);
    int cnt  = wtot[g][0] + wtot[g][1];

    {
        int p = excl;
        uint32_t m = a;
        while (m) {
            int b = __ffs(m) - 1; m &= m - 1;
            nbr[g][p++] = (uint16_t)((w << 5) + b);
        }
    }
    __syncthreads();

    uint32_t acc = a;
    const uint16_t* nl = nbr[g];
    int j = 0;
    for (; j + 8 <= cnt; j += 8) {
        uint32_t v0 = g_adj[(int)nl[j+0] * W + w];
        uint32_t v1 = g_adj[(int)nl[j+1] * W + w];
        uint32_t v2 = g_adj[(int)nl[j+2] * W + w];
        uint32_t v3 = g_adj[(int)nl[j+3] * W + w];
        uint32_t v4 = g_adj[(int)nl[j+4] * W + w];
        uint32_t v5 = g_adj[(int)nl[j+5] * W + w];
        uint32_t v6 = g_adj[(int)nl[j+6] * W + w];
        uint32_t v7 = g_adj[(int)nl[j+7] * W + w];
        acc |= (v0 | v1) | (v2 | v3) | ((v4 | v5) | (v6 | v7));
    }
    for (; j < cnt; j++)
        acc |= g_adj[(int)nl[j] * W + w];

    uint32_t self = (w == (r >> 5)) ? (1u << (r & 31)) : 0u;
    uint32_t comb = a | (acc & ~self);
    g_comb[r * W + w] = comb;        // k_attr needs it

    int t = __popc(comb);
    #pragma unroll
    for (int o = 16; o; o >>= 1) t += __shfl_down_sync(0xffffffffu, t, o);
    __syncthreads();                 // wtot reuse barrier not needed; rcnt write next
    if (lane == 0) wtot[g][hw] = t;  // reuse wtot as temp for the 2-warp sum
    __syncthreads();
    if (w == 0) rcnt[g] = wtot[g][0] + wtot[g][1];
    __syncthreads();

    // ---- Phase B: decoupled lookback --------------------------------------
    int bsum = rcnt[0] + rcnt[1] + rcnt[2] + rcnt[3];

    if (tid == 0) {
        unsigned long long v = bid == 0
            ? ((2ull << 32) | (unsigned)bsum)       // block 0: final prefix
            : ((1ull << 32) | (unsigned)bsum);      // aggregate available
        atomicExch(&g_status[bid], v);
    }

    if (tid < 32) {
        long long running = 0;
        bool done = (bid == 0);
        int base = bid - 32;                         // window [base, base+31]
        while (!done) {
            int jj = base + tid;
            unsigned long long s = (jj >= 0)
                ? *(volatile unsigned long long*)&g_status[jj]
                : (2ull << 32);                      // virtual prefix=0
            unsigned flag = (unsigned)(s >> 32);
            unsigned val  = (unsigned)s;

            unsigned pmask = __ballot_sync(0xffffffffu, flag == 2u);
            unsigned amask = __ballot_sync(0xffffffffu, flag >= 1u);
            if (pmask) {
                int pl = 31 - __clz(pmask);          // prefix closest to bid
                unsigned need = 0xffffffffu << pl;   // lanes pl..31 must be ready
                if ((amask & need) == need) {
                    int contrib = (tid >= pl) ? (int)val : 0;
                    #pragma unroll
                    for (int o = 16; o; o >>= 1)
                        contrib += __shfl_down_sync(0xffffffffu, contrib, o);
                    running += __shfl_sync(0xffffffffu, contrib, 0);
                    done = true;
                }
            } else if (amask == 0xffffffffu) {
                int contrib = (int)val;
                #pragma unroll
                for (int o = 16; o; o >>= 1)
                    contrib += __shfl_down_sync(0xffffffffu, contrib, o);
                running += __shfl_sync(0xffffffffu, contrib, 0);
                base -= 32;
            }
            // else: spin, re-read same window
        }
        if (tid == 0) {
            sbexcl = (int)running;
            if (bid != 0)
                atomicExch(&g_status[bid],
                           (2ull << 32) | (unsigned)(running + bsum));
        } else if (bid == 0 && tid == 0) { /* unreachable */ }
        if (bid == 0 && tid == 0) sbexcl = 0;
    }
    __syncthreads();

    // ---- Phase C: emit -----------------------------------------------------
    int row_base = sbexcl;
    #pragma unroll
    for (int q = 0; q < 4; q++) {
        if (q == g) break;
        row_base += rcnt[q];
    }
    if (w == 0) g_off[r] = row_base;

    // word-exclusive scan of popc(comb) within the 64-thread row
    int epc = __popc(comb);
    int ex = epc;
    #pragma unroll
    for (int o = 1; o < 32; o <<= 1) {
        int v = __shfl_up_sync(0xffffffffu, ex, o);
        if (lane >= o) ex += v;
    }
    if (lane == 31) etot[g][hw] = ex;
    __syncthreads();
    int wexcl = ex - epc + (hw ? etot[g][0] : 0);

    int p = row_base + wexcl;
    float* rows = out;
    float* cols = out + emax;
    float fr = (float)r;
    uint32_t c = comb;
    while (c) {
        int b = __ffs(c) - 1; c &= c - 1;
        if (p >= emax) break;
        rows[p] = fr;
        cols[p] = (float)((w << 5) + b);
        p++;
    }
}

// ---------------------------------------------------------------------------
// attr: rank each input edge in its combined row, atomicAdd features.
// Also re-zeroes g_adj (exactly 32768 threads x uint4 = 512KB).
// ---------------------------------------------------------------------------
__global__ void k_attr(const int* __restrict__ src,
                       const int* __restrict__ dst,
                       const float* __restrict__ attr,
                       float* __restrict__ out, int emax, int E)
{
    int e = blockIdx.x * blockDim.x + threadIdx.x;

    if (e * 4 < NN * W)
        ((uint4*)g_adj)[e] = make_uint4(0u, 0u, 0u, 0u);

    if (e >= E) return;
    int s = src[e], d = dst[e];
    const uint32_t* row = &g_comb[s * W];

    int wd = d >> 5;
    int cnt = 0;
    for (int jj = 0; jj < wd; jj++) cnt += __popc(row[jj]);
    cnt += __popc(row[wd] & ((1u << (d & 31)) - 1u));

    int p = g_off[s] + cnt;
    if (p >= emax) return;

    float* oa = out + (int64_t)emax * 2 + (int64_t)p * FDIM;
    const float* ia = attr + (int64_t)e * FDIM;
    #pragma unroll
    for (int f = 0; f < FDIM; f++)
        atomicAdd(&oa[f], ia[f]);
}

// ---------------------------------------------------------------------------
// Host-side resources (host objects only; created once at process start)
// ---------------------------------------------------------------------------
static cudaStream_t s_side;
static cudaEvent_t  ev_fork, ev_init;
struct _ResInit {
    _ResInit() {
        cudaStreamCreateWithFlags(&s_side, cudaStreamNonBlocking);
        cudaEventCreateWithFlags(&ev_fork, cudaEventDisableTiming);
        cudaEventCreateWithFlags(&ev_init, cudaEventDisableTiming);
    }
};
static _ResInit _res_init_once;

extern "C" void kernel_launch(void* const* d_in, const int* in_sizes, int n_in,
                              void* d_out, int out_size)
{
    const int*   ei   = (const int*)d_in[1];
    const float* attr = (const float*)d_in[2];
    const int E    = in_sizes[1] / 2;
    const int emax = out_size / (2 + FDIM);
    float* out = (float*)d_out;

    // side branch: big 42MB output init, overlapped with adjacency build
    cudaEventRecord(ev_fork, 0);
    cudaStreamWaitEvent(s_side, ev_fork, 0);
    k_init<<<1024, 256, 0, s_side>>>(out, emax);
    cudaEventRecord(ev_init, s_side);

    // main: scatter -> fused(expand+scan+emit, after init) -> attr
    k_scatter<<<(E + 255) / 256, 256>>>(ei, ei + E, E);
    cudaStreamWaitEvent(0, ev_init, 0);
    k_fused<<<NB, 256>>>(out, emax);
    k_attr<<<(E + 127) / 128, 128>>>(ei, ei + E, attr, out, emax, E);
}

// round 6
// speedup vs baseline: 1.1646x; 1.1646x over previous
#include <cuda_runtime.h>
#include <stdint.h>

#define NN   2048          // num_nodes
#define W    64            // words per bitmask row = NN/32
#define FDIM 8             // edge feature dim
#define NB   512           // fused-kernel blocks (NN/4)

__device__ uint32_t g_adj    [NN * W];   // zero at load; re-zeroed by k_attr
__device__ uint32_t g_comb   [NN * W];
__device__ int      g_wordoff[NN * W];   // global output pos of first bit in word
__device__ unsigned long long g_status[NB];   // lookback: (flag<<32)|count

// ---------------------------------------------------------------------------
// init: fill index region with -1.0f, attr region with 0.0f  (side stream)
// ---------------------------------------------------------------------------
__global__ void k_init(float* __restrict__ out, int emax)
{
    const int64_t idx_words = (int64_t)emax * 2;
    const int64_t total     = (int64_t)emax * (2 + FDIM);
    const int64_t n4        = total >> 2;
    const float4 neg = make_float4(-1.f, -1.f, -1.f, -1.f);
    const float4 zer = make_float4( 0.f,  0.f,  0.f,  0.f);

    int64_t stride = (int64_t)gridDim.x * blockDim.x;
    for (int64_t i = (int64_t)blockIdx.x * blockDim.x + threadIdx.x;
         i < n4; i += stride)
        ((float4*)out)[i] = ((i << 2) < idx_words) ? neg : zer;
}

// ---------------------------------------------------------------------------
// scatter: set adjacency bits; also reset lookback statuses for this call
// ---------------------------------------------------------------------------
__global__ void k_scatter(const int* __restrict__ src,
                          const int* __restrict__ dst, int E)
{
    int e = blockIdx.x * blockDim.x + threadIdx.x;
    if (e < NB) g_status[e] = 0ull;
    if (e >= E) return;
    int s = src[e], d = dst[e];
    atomicOr(&g_adj[s * W + (d >> 5)], 1u << (d & 31));
}

// ---------------------------------------------------------------------------
// fused: expand + decoupled-lookback scan + emit (+ g_wordoff for k_attr)
// ---------------------------------------------------------------------------
__global__ __launch_bounds__(256) void k_fused(float* __restrict__ out, int emax)
{
    __shared__ uint16_t nbr[4][NN];
    __shared__ int wtot[4][2];
    __shared__ int etot[4][2];
    __shared__ int rcnt[4];
    __shared__ int sbexcl;

    const int tid  = threadIdx.x;
    const int bid  = blockIdx.x;
    const int g    = tid >> 6;
    const int w    = tid & 63;
    const int r    = (bid << 2) + g;
    const int lane = w & 31, hw = w >> 5;

    // ---- Phase A: expand ---------------------------------------------------
    uint32_t a = g_adj[r * W + w];

    int pc = __popc(a);
    int x = pc;
    #pragma unroll
    for (int o = 1; o < 32; o <<= 1) {
        int v = __shfl_up_sync(0xffffffffu, x, o);
        if (lane >= o) x += v;
    }
    if (lane == 31) wtot[g][hw] = x;
    __syncthreads();
    int excl = x - pc + (hw ? wtot[g][0] : 0);
    int cnt  = wtot[g][0] + wtot[g][1];

    {
        int p = excl;
        uint32_t m = a;
        while (m) {
            int b = __ffs(m) - 1; m &= m - 1;
            nbr[g][p++] = (uint16_t)((w << 5) + b);
        }
    }
    __syncthreads();

    uint32_t acc = a;
    const uint16_t* nl = nbr[g];
    int j = 0;
    for (; j + 8 <= cnt; j += 8) {
        uint32_t v0 = g_adj[(int)nl[j+0] * W + w];
        uint32_t v1 = g_adj[(int)nl[j+1] * W + w];
        uint32_t v2 = g_adj[(int)nl[j+2] * W + w];
        uint32_t v3 = g_adj[(int)nl[j+3] * W + w];
        uint32_t v4 = g_adj[(int)nl[j+4] * W + w];
        uint32_t v5 = g_adj[(int)nl[j+5] * W + w];
        uint32_t v6 = g_adj[(int)nl[j+6] * W + w];
        uint32_t v7 = g_adj[(int)nl[j+7] * W + w];
        acc |= (v0 | v1) | (v2 | v3) | ((v4 | v5) | (v6 | v7));
    }
    for (; j < cnt; j++)
        acc |= g_adj[(int)nl[j] * W + w];

    uint32_t self = (w == (r >> 5)) ? (1u << (r & 31)) : 0u;
    uint32_t comb = a | (acc & ~self);
    g_comb[r * W + w] = comb;

    int t = __popc(comb);
    #pragma unroll
    for (int o = 16; o; o >>= 1) t += __shfl_down_sync(0xffffffffu, t, o);
    __syncthreads();
    if (lane == 0) wtot[g][hw] = t;
    __syncthreads();
    if (w == 0) rcnt[g] = wtot[g][0] + wtot[g][1];
    __syncthreads();

    // ---- Phase B: decoupled lookback --------------------------------------
    int bsum = rcnt[0] + rcnt[1] + rcnt[2] + rcnt[3];

    if (tid == 0) {
        unsigned long long v = bid == 0
            ? ((2ull << 32) | (unsigned)bsum)
            : ((1ull << 32) | (unsigned)bsum);
        atomicExch(&g_status[bid], v);
    }

    if (tid < 32) {
        long long running = 0;
        bool done = (bid == 0);
        int base = bid - 32;
        while (!done) {
            int jj = base + tid;
            unsigned long long s = (jj >= 0)
                ? *(volatile unsigned long long*)&g_status[jj]
                : (2ull << 32);
            unsigned flag = (unsigned)(s >> 32);
            unsigned val  = (unsigned)s;

            unsigned pmask = __ballot_sync(0xffffffffu, flag == 2u);
            unsigned amask = __ballot_sync(0xffffffffu, flag >= 1u);
            if (pmask) {
                int pl = 31 - __clz(pmask);
                unsigned need = 0xffffffffu << pl;
                if ((amask & need) == need) {
                    int contrib = (tid >= pl) ? (int)val : 0;
                    #pragma unroll
                    for (int o = 16; o; o >>= 1)
                        contrib += __shfl_down_sync(0xffffffffu, contrib, o);
                    running += __shfl_sync(0xffffffffu, contrib, 0);
                    done = true;
                }
            } else if (amask == 0xffffffffu) {
                int contrib = (int)val;
                #pragma unroll
                for (int o = 16; o; o >>= 1)
                    contrib += __shfl_down_sync(0xffffffffu, contrib, o);
                running += __shfl_sync(0xffffffffu, contrib, 0);
                base -= 32;
            }
        }
        if (tid == 0) {
            sbexcl = (int)running;
            if (bid != 0)
                atomicExch(&g_status[bid],
                           (2ull << 32) | (unsigned)(running + bsum));
        }
        if (bid == 0 && tid == 0) sbexcl = 0;
    }
    __syncthreads();

    // ---- Phase C: emit + publish word offsets ------------------------------
    int row_base = sbexcl;
    #pragma unroll
    for (int q = 0; q < 4; q++) {
        if (q == g) break;
        row_base += rcnt[q];
    }

    int epc = __popc(comb);
    int ex = epc;
    #pragma unroll
    for (int o = 1; o < 32; o <<= 1) {
        int v = __shfl_up_sync(0xffffffffu, ex, o);
        if (lane >= o) ex += v;
    }
    if (lane == 31) etot[g][hw] = ex;
    __syncthreads();
    int wexcl = ex - epc + (hw ? etot[g][0] : 0);

    int p = row_base + wexcl;
    g_wordoff[r * W + w] = p;        // O(1) edge ranking for k_attr

    float* rows = out;
    float* cols = out + emax;
    float fr = (float)r;
    uint32_t c = comb;
    while (c) {
        int b = __ffs(c) - 1; c &= c - 1;
        if (p >= emax) break;
        rows[p] = fr;
        cols[p] = (float)((w << 5) + b);
        p++;
    }
}

// ---------------------------------------------------------------------------
// attr: O(1) rank via g_wordoff, 2x vector red per edge; re-zeroes g_adj
// ---------------------------------------------------------------------------
__global__ void k_attr(const int* __restrict__ src,
                       const int* __restrict__ dst,
                       const float* __restrict__ attr,
                       float* __restrict__ out, int emax, int E)
{
    int e = blockIdx.x * blockDim.x + threadIdx.x;

    if (e * 4 < NN * W)
        ((uint4*)g_adj)[e] = make_uint4(0u, 0u, 0u, 0u);

    if (e >= E) return;
    int s = src[e], d = dst[e];
    int idx = s * W + (d >> 5);

    int p = g_wordoff[idx]
          + __popc(g_comb[idx] & ((1u << (d & 31)) - 1u));
    if (p >= emax) return;

    const float4* ia = (const float4*)(attr + (int64_t)e * FDIM);
    float4 a0 = ia[0], a1 = ia[1];
    float* oa = out + (int64_t)emax * 2 + (int64_t)p * FDIM;

    asm volatile("red.global.add.v4.f32 [%0], {%1,%2,%3,%4};"
                 :: "l"(oa), "f"(a0.x), "f"(a0.y), "f"(a0.z), "f"(a0.w)
                 : "memory");
    asm volatile("red.global.add.v4.f32 [%0], {%1,%2,%3,%4};"
                 :: "l"(oa + 4), "f"(a1.x), "f"(a1.y), "f"(a1.z), "f"(a1.w)
                 : "memory");
}

// ---------------------------------------------------------------------------
// Host-side resources (host objects only; created once at process start)
// ---------------------------------------------------------------------------
static cudaStream_t s_side;
static cudaEvent_t  ev_fork, ev_init;
struct _ResInit {
    _ResInit() {
        cudaStreamCreateWithFlags(&s_side, cudaStreamNonBlocking);
        cudaEventCreateWithFlags(&ev_fork, cudaEventDisableTiming);
        cudaEventCreateWithFlags(&ev_init, cudaEventDisableTiming);
    }
};
static _ResInit _res_init_once;

extern "C" void kernel_launch(void* const* d_in, const int* in_sizes, int n_in,
                              void* d_out, int out_size)
{
    const int*   ei   = (const int*)d_in[1];
    const float* attr = (const float*)d_in[2];
    const int E    = in_sizes[1] / 2;
    const int emax = out_size / (2 + FDIM);
    float* out = (float*)d_out;

    // side branch: big 42MB output init, overlapped with adjacency build
    cudaEventRecord(ev_fork, 0);
    cudaStreamWaitEvent(s_side, ev_fork, 0);
    k_init<<<1024, 256, 0, s_side>>>(out, emax);
    cudaEventRecord(ev_init, s_side);

    // main: scatter -> fused(expand+scan+emit, after init) -> attr
    k_scatter<<<(E + 255) / 256, 256>>>(ei, ei + E, E);
    cudaStreamWaitEvent(0, ev_init, 0);
    k_fused<<<NB, 256>>>(out, emax);
    k_attr<<<(E + 127) / 128, 128>>>(ei, ei + E, attr, out, emax, E);
}